// round 5
// baseline (speedup 1.0000x reference)
#include <cuda_runtime.h>
#include <stdint.h>

#define NUM_CLASSES 32000
#define C4 (NUM_CLASSES / 4)        // 8000 float4 slots per row
#define ALPHA 0.95f
#define THREADS 1024
#define EIT 8                       // float4s per thread per row (8*1024 = 8192 >= 8000)
#define SMEM_BYTES (C4 * 16)        // 128000 B: odd-row staging

// Flag: 1 if labels buffer is int64, 0 if int32. Set by detect_kernel.
__device__ int g_lab_is_64 = 0;

// Interpret the first 64 entries as uint64. If truly int64 they are labels
// < 32000 -> flag=1. If truly int32, each u64 pairs two labels and is < 32000
// only when the odd-position label is 0: P(all 32) ~ (1/32000)^32 ~ 0.
__global__ void detect_kernel(const unsigned long long* __restrict__ labels) {
    int bad = (labels[threadIdx.x] >= (unsigned long long)NUM_CLASSES) ? 1 : 0;
    #pragma unroll
    for (int off = 16; off > 0; off >>= 1)
        bad |= __shfl_down_sync(0xffffffffu, bad, off);
    bad |= __shfl_sync(0xffffffffu, bad, 0);
    if (threadIdx.x == 0) g_lab_is_64 = bad ? 0 : 1;
}

__device__ __forceinline__ int load_label(const void* labels, int row, int is64) {
    if (is64) return (int)(((const long long*)labels)[row]);
    return ((const int*)labels)[row];
}

// Persistent pair-pipelined kernel. Each CTA (one per SM) loops over row PAIRS:
//   even row lives in registers (8 float4/thread), odd row in smem
//   (thread-private slots). One block barrier per pair. The next pair's
//   even-row loads are issued between the two store phases.
__global__ __launch_bounds__(THREADS, 1)
void distill_kernel(const float* __restrict__ x,
                    const void*  __restrict__ labels,
                    float*       __restrict__ out,
                    int npairs) {
    extern __shared__ float4 s4[];          // C4 slots, thread-private mapping
    __shared__ float warp_e[THREADS / 32];
    __shared__ float warp_o[THREADS / 32];
    __shared__ float s_red[2];

    const int tid  = threadIdx.x;
    const int lane = tid & 31;
    const int wid  = tid >> 5;
    const int is64 = g_lab_is_64;

    int p = blockIdx.x;                     // pair index; strides by gridDim.x

    float4 v[EIT];
    float  sum_e = 0.0f;
    int    lab_e = 0;
    float  t_e   = 0.0f;

    // ---- Prologue: load first even row into registers ----
    if (p < npairs) {
        const int row_e = 2 * p;
        lab_e = load_label(labels, row_e, is64);
        t_e = __ldg(x + (size_t)row_e * NUM_CLASSES + lab_e);
        const float4* __restrict__ xr = reinterpret_cast<const float4*>(x + (size_t)row_e * NUM_CLASSES);
        #pragma unroll
        for (int k = 0; k < EIT; k++) {
            const int i = tid + k * THREADS;
            if (k < EIT - 1 || i < C4) {
                v[k] = __ldcs(&xr[i]);
                sum_e += (v[k].x + v[k].y) + (v[k].z + v[k].w);
            }
        }
    }

    while (p < npairs) {
        const int row_e = 2 * p;
        const int row_o = 2 * p + 1;

        // ---- Load odd row into smem (thread-private slots), accumulate sum ----
        const int lab_o = load_label(labels, row_o, is64);
        const float t_o = __ldg(x + (size_t)row_o * NUM_CLASSES + lab_o);
        float sum_o = 0.0f;
        {
            const float4* __restrict__ xr = reinterpret_cast<const float4*>(x + (size_t)row_o * NUM_CLASSES);
            #pragma unroll
            for (int k = 0; k < EIT; k++) {
                const int i = tid + k * THREADS;
                if (k < EIT - 1 || i < C4) {
                    float4 w = __ldcs(&xr[i]);
                    s4[i] = w;
                    sum_o += (w.x + w.y) + (w.z + w.w);
                }
            }
        }

        // ---- Reduce BOTH sums in one barrier pass ----
        {
            float a = sum_e, b = sum_o;
            #pragma unroll
            for (int off = 16; off > 0; off >>= 1) {
                a += __shfl_down_sync(0xffffffffu, a, off);
                b += __shfl_down_sync(0xffffffffu, b, off);
            }
            if (lane == 0) { warp_e[wid] = a; warp_o[wid] = b; }
        }
        __syncthreads();
        if (wid == 0) {
            float ra = warp_e[lane];
            float rb = warp_o[lane];
            #pragma unroll
            for (int off = 16; off > 0; off >>= 1) {
                ra += __shfl_down_sync(0xffffffffu, ra, off);
                rb += __shfl_down_sync(0xffffffffu, rb, off);
            }
            if (lane == 0) { s_red[0] = ra; s_red[1] = rb; }
        }
        __syncthreads();

        const float S_e = s_red[0];
        const float S_o = s_red[1];
        const float sc_e = ALPHA / (1.0f + S_e - 2.0f * t_e);
        const float co_e = 1.0f - sc_e * S_e;
        const float sc_o = ALPHA / (1.0f + S_o - 2.0f * t_o);
        const float co_o = 1.0f - sc_o * S_o;
        const int lab4_e = lab_e >> 2, labc_e = lab_e & 3;
        const int lab4_o = lab_o >> 2, labc_o = lab_o & 3;

        // ---- Store even row from registers (frees regs) ----
        {
            float4* __restrict__ orow = reinterpret_cast<float4*>(out + (size_t)row_e * NUM_CLASSES);
            #pragma unroll
            for (int k = 0; k < EIT; k++) {
                const int i = tid + k * THREADS;
                if (k < EIT - 1 || i < C4) {
                    float4 o;
                    o.x = sc_e * v[k].x;
                    o.y = sc_e * v[k].y;
                    o.z = sc_e * v[k].z;
                    o.w = sc_e * v[k].w;
                    if (i == lab4_e) reinterpret_cast<float*>(&o)[labc_e] += co_e;
                    __stcs(&orow[i], o);
                }
            }
        }

        // ---- Pipeline: issue NEXT pair's even-row loads now ----
        const int pn = p + gridDim.x;
        sum_e = 0.0f;
        if (pn < npairs) {
            const int row_en = 2 * pn;
            lab_e = load_label(labels, row_en, is64);
            t_e = __ldg(x + (size_t)row_en * NUM_CLASSES + lab_e);
            const float4* __restrict__ xr = reinterpret_cast<const float4*>(x + (size_t)row_en * NUM_CLASSES);
            #pragma unroll
            for (int k = 0; k < EIT; k++) {
                const int i = tid + k * THREADS;
                if (k < EIT - 1 || i < C4) {
                    v[k] = __ldcs(&xr[i]);
                    sum_e += (v[k].x + v[k].y) + (v[k].z + v[k].w);
                }
            }
        }

        // ---- Store odd row from smem ----
        {
            float4* __restrict__ orow = reinterpret_cast<float4*>(out + (size_t)row_o * NUM_CLASSES);
            #pragma unroll
            for (int k = 0; k < EIT; k++) {
                const int i = tid + k * THREADS;
                if (k < EIT - 1 || i < C4) {
                    float4 w = s4[i];
                    float4 o;
                    o.x = sc_o * w.x;
                    o.y = sc_o * w.y;
                    o.z = sc_o * w.z;
                    o.w = sc_o * w.w;
                    if (i == lab4_o) reinterpret_cast<float*>(&o)[labc_o] += co_o;
                    __stcs(&orow[i], o);
                }
            }
        }

        p = pn;
    }
}

extern "C" void kernel_launch(void* const* d_in, const int* in_sizes, int n_in,
                              void* d_out, int out_size) {
    const float* teacher_logits = (const float*)d_in[0];
    const void*  true_labels    = d_in[1];
    float* out = (float*)d_out;

    const int batch  = in_sizes[1];     // 4096 rows
    const int npairs = batch / 2;

    int dev = 0, nsm = 148;
    cudaGetDevice(&dev);
    cudaDeviceGetAttribute(&nsm, cudaDevAttrMultiProcessorCount, dev);

    cudaFuncSetAttribute(distill_kernel,
                         cudaFuncAttributeMaxDynamicSharedMemorySize, SMEM_BYTES);

    detect_kernel<<<1, 64>>>((const unsigned long long*)true_labels);
    distill_kernel<<<nsm, THREADS, SMEM_BYTES>>>(teacher_logits, true_labels, out, npairs);
}

// round 6
// speedup vs baseline: 1.0039x; 1.0039x over previous
#include <cuda_runtime.h>
#include <stdint.h>

#define NUM_CLASSES 32000
#define C4 (NUM_CLASSES / 4)        // 8000 float4 slots per row
#define ALPHA 0.95f
#define THREADS 384
#define RITEMS 9                    // float4s per thread in registers (9*384 = 3456 slots)
#define RSLOTS (RITEMS * THREADS)   // 3456
#define SSLOTS (C4 - RSLOTS)        // 4544 slots in smem
#define SITER  ((SSLOTS + THREADS - 1) / THREADS)   // 12 (last partial)
#define SMEM_STAGE_BYTES (SSLOTS * 16)              // 72704 B per CTA

// Flag: 1 if labels buffer is int64, 0 if int32. Set by detect_kernel.
__device__ int g_lab_is_64 = 0;

// Interpret the first 64 entries as uint64. If truly int64 they are labels
// < 32000 -> flag=1. If truly int32, each u64 pairs two labels and is < 32000
// only when the odd-position label is 0: P(all 32) ~ (1/32000)^32 ~ 0.
__global__ void detect_kernel(const unsigned long long* __restrict__ labels) {
    int bad = (labels[threadIdx.x] >= (unsigned long long)NUM_CLASSES) ? 1 : 0;
    #pragma unroll
    for (int off = 16; off > 0; off >>= 1)
        bad |= __shfl_down_sync(0xffffffffu, bad, off);
    bad |= __shfl_sync(0xffffffffu, bad, 0);
    if (threadIdx.x == 0) g_lab_is_64 = bad ? 0 : 1;
}

// 3 CTAs per SM, each an independent barrier domain: while one CTA sits in its
// load-tail + reduce, the other two keep issuing memory ops. Row staged once
// (9 float4 in regs + 4544 float4 in smem, thread-private slots, no extra
// barrier); exactly 1 DRAM read + 1 DRAM write per element.
__global__ __launch_bounds__(THREADS, 3)
void distill_kernel(const float* __restrict__ x,
                    const void*  __restrict__ labels,
                    float*       __restrict__ out) {
    extern __shared__ float4 s4[];                  // SSLOTS, thread-private mapping
    __shared__ float warp_sums[THREADS / 32];       // 12
    __shared__ float s_S;

    const int row = blockIdx.x;
    const int tid = threadIdx.x;

    const float4* __restrict__ xr   = reinterpret_cast<const float4*>(x + (size_t)row * NUM_CLASSES);
    float4*       __restrict__ orow = reinterpret_cast<float4*>(out + (size_t)row * NUM_CLASSES);

    // Label + t early so their latency hides under the bulk loads.
    int lab;
    if (g_lab_is_64) lab = (int)(((const long long*)labels)[row]);
    else             lab = ((const int*)labels)[row];
    const float t = __ldg(x + (size_t)row * NUM_CLASSES + lab);

    // ---- Phase 1a: 9 float4/thread into registers ----
    float4 v[RITEMS];
    float sum = 0.0f;
    #pragma unroll
    for (int k = 0; k < RITEMS; k++) {
        v[k] = __ldcs(&xr[tid + k * THREADS]);
        sum += (v[k].x + v[k].y) + (v[k].z + v[k].w);
    }
    // ---- Phase 1b: remaining 4544 float4 staged in smem (thread-private slots) ----
    #pragma unroll
    for (int k = 0; k < SITER; k++) {
        const int j = tid + k * THREADS;
        if (k < SITER - 1 || j < SSLOTS) {
            float4 w = __ldcs(&xr[RSLOTS + j]);
            s4[j] = w;
            sum += (w.x + w.y) + (w.z + w.w);
        }
    }

    // Block reduce across 12 warps.
    #pragma unroll
    for (int off = 16; off > 0; off >>= 1)
        sum += __shfl_down_sync(0xffffffffu, sum, off);
    const int lane = tid & 31;
    const int wid  = tid >> 5;
    if (lane == 0) warp_sums[wid] = sum;
    __syncthreads();
    if (wid == 0) {
        float r = (lane < THREADS / 32) ? warp_sums[lane] : 0.0f;
        #pragma unroll
        for (int off = 8; off > 0; off >>= 1)
            r += __shfl_down_sync(0xffffffffu, r, off);
        if (lane == 0) s_S = r;
    }
    __syncthreads();

    const float S = s_S;
    const float s = ALPHA / (1.0f + S - 2.0f * t);
    const float corr = 1.0f - s * S;

    const int lab4 = lab >> 2;
    const int labc = lab & 3;

    // ---- Phase 2a: scale registers, fused label correction, streaming stores ----
    #pragma unroll
    for (int k = 0; k < RITEMS; k++) {
        const int i = tid + k * THREADS;
        float4 o;
        o.x = s * v[k].x;
        o.y = s * v[k].y;
        o.z = s * v[k].z;
        o.w = s * v[k].w;
        if (i == lab4) reinterpret_cast<float*>(&o)[labc] += corr;
        __stcs(&orow[i], o);
    }
    // ---- Phase 2b: scale smem-staged part ----
    #pragma unroll
    for (int k = 0; k < SITER; k++) {
        const int j = tid + k * THREADS;
        if (k < SITER - 1 || j < SSLOTS) {
            float4 w = s4[j];
            const int i = RSLOTS + j;
            float4 o;
            o.x = s * w.x;
            o.y = s * w.y;
            o.z = s * w.z;
            o.w = s * w.w;
            if (i == lab4) reinterpret_cast<float*>(&o)[labc] += corr;
            __stcs(&orow[i], o);
        }
    }
}

extern "C" void kernel_launch(void* const* d_in, const int* in_sizes, int n_in,
                              void* d_out, int out_size) {
    const float* teacher_logits = (const float*)d_in[0];
    const void*  true_labels    = d_in[1];
    float* out = (float*)d_out;

    const int batch = in_sizes[1];   // 4096 rows (label count)

    cudaFuncSetAttribute(distill_kernel,
                         cudaFuncAttributeMaxDynamicSharedMemorySize, SMEM_STAGE_BYTES);

    detect_kernel<<<1, 64>>>((const unsigned long long*)true_labels);
    distill_kernel<<<batch, THREADS, SMEM_STAGE_BYTES>>>(teacher_logits, true_labels, out);
}